// round 1
// baseline (speedup 1.0000x reference)
#include <cuda_runtime.h>
#include <cuda_bf16.h>

// DCT over contiguous 64-float groups: out = C^T * X * C per 8x8 "patch"
// (the reference's reshape(b,-1,64) takes CONTIGUOUS runs of 64 floats,
//  so global access is fully linear/coalescible).
//
// Separable form: 1024 FMAs/patch instead of 4096 for the 64x64 GEMM.
// Memory-bound target: ~201 MB HBM traffic.

#define TPB 256          // threads per block = patches per block
#define PAD 65           // floats per patch slot in smem (conflict-free columns)

// C[u][i] = s(u) * cos((2i+1) * u * pi / 16), s(0)=sqrt(1/8), s(u>0)=0.5
__device__ __constant__ __align__(16) float const_unused = 0.f; // (none needed)

__device__ __forceinline__ float dct_c(int u, int i) {
    // fully-unrolled callers => compile-time constants => immediates in SASS
    const float T[8][8] = {
        { 0.35355339f,  0.35355339f,  0.35355339f,  0.35355339f,  0.35355339f,  0.35355339f,  0.35355339f,  0.35355339f},
        { 0.49039264f,  0.41573481f,  0.27778512f,  0.09754516f, -0.09754516f, -0.27778512f, -0.41573481f, -0.49039264f},
        { 0.46193977f,  0.19134172f, -0.19134172f, -0.46193977f, -0.46193977f, -0.19134172f,  0.19134172f,  0.46193977f},
        { 0.41573481f, -0.09754516f, -0.49039264f, -0.27778512f,  0.27778512f,  0.49039264f,  0.09754516f, -0.41573481f},
        { 0.35355339f, -0.35355339f, -0.35355339f,  0.35355339f,  0.35355339f, -0.35355339f, -0.35355339f,  0.35355339f},
        { 0.27778512f, -0.49039264f,  0.09754516f,  0.41573481f, -0.41573481f, -0.09754516f,  0.49039264f, -0.27778512f},
        { 0.19134172f, -0.46193977f,  0.46193977f, -0.19134172f, -0.19134172f,  0.46193977f, -0.46193977f,  0.19134172f},
        { 0.09754516f, -0.27778512f,  0.41573481f, -0.49039264f,  0.49039264f, -0.41573481f,  0.27778512f, -0.09754516f},
    };
    return T[u][i];
}

__global__ void __launch_bounds__(TPB, 2)
dct_kernel(const float* __restrict__ in, float* __restrict__ out) {
    __shared__ float s[TPB * PAD];

    const size_t base = (size_t)blockIdx.x * (TPB * 64);
    const int t = threadIdx.x;

    // ---- Stage 1: coalesced global load -> padded smem -------------------
    const float4* __restrict__ in4 = (const float4*)(in + base);
#pragma unroll
    for (int n = 0; n < 16; ++n) {
        int idx4 = n * TPB + t;
        float4 v = in4[idx4];
        int e = idx4 * 4;          // float index within block's 16384 floats
        int p = e >> 6;            // patch
        int k = e & 63;            // element within patch (multiple of 4)
        float* dst = &s[p * PAD + k];
        dst[0] = v.x; dst[1] = v.y; dst[2] = v.z; dst[3] = v.w;
    }
    __syncthreads();

    // ---- Stage 2: per-thread 8x8 separable DCT ---------------------------
    // X[u][v] = s[t*PAD + u*8 + v]  (bank-conflict-free: (t*65+c)%32 = (t+c)%32)
    float* X = &s[t * PAD];

    float tmp[8][8];               // tmp[i][v] = sum_u C[u][i] * X[u][v]
#pragma unroll
    for (int u = 0; u < 8; ++u) {
        float xr[8];
#pragma unroll
        for (int v = 0; v < 8; ++v) xr[v] = X[u * 8 + v];
#pragma unroll
        for (int i = 0; i < 8; ++i) {
            const float c = dct_c(u, i);
#pragma unroll
            for (int v = 0; v < 8; ++v) {
                if (u == 0) tmp[i][v] = c * xr[v];
                else        tmp[i][v] = fmaf(c, xr[v], tmp[i][v]);
            }
        }
    }

    // out[i][j] = sum_v tmp[i][v] * C[v][j]; write back in-place (this thread
    // is the only reader/writer of its own patch slot after stage 1).
#pragma unroll
    for (int i = 0; i < 8; ++i) {
#pragma unroll
        for (int j = 0; j < 8; ++j) {
            float o = tmp[i][0] * dct_c(0, j);
#pragma unroll
            for (int v = 1; v < 8; ++v)
                o = fmaf(tmp[i][v], dct_c(v, j), o);
            X[i * 8 + j] = o;
        }
    }
    __syncthreads();

    // ---- Stage 3: padded smem -> coalesced global store ------------------
    float4* __restrict__ out4 = (float4*)(out + base);
#pragma unroll
    for (int n = 0; n < 16; ++n) {
        int idx4 = n * TPB + t;
        int e = idx4 * 4;
        int p = e >> 6;
        int k = e & 63;
        const float* src = &s[p * PAD + k];
        out4[idx4] = make_float4(src[0], src[1], src[2], src[3]);
    }
}

extern "C" void kernel_launch(void* const* d_in, const int* in_sizes, int n_in,
                              void* d_out, int out_size) {
    const float* in = (const float*)d_in[0];   // (8,3,1024,1024) fp32
    float* out = (float*)d_out;                // same shape fp32
    // total floats = 25,165,824 = 1536 blocks * (256 patches * 64 floats)
    int total = in_sizes[0];
    int blocks = total / (TPB * 64);
    dct_kernel<<<blocks, TPB>>>(in, out);
}

// round 3
// speedup vs baseline: 1.1055x; 1.1055x over previous
#include <cuda_runtime.h>
#include <cuda_bf16.h>

// 8x8 DCT on contiguous 64-float patches: out = C^T X C (separable).
// 2 threads per patch using the symmetry C[u][7-i] = (-1)^u C[u][i].
// Thread h=0 computes output rows 0..3, thread h=1 computes rows 7..4 with the
// SAME immediate constants (sign folded into odd input rows). Halves register
// pressure (tmp is 4x8) and smem (33KB/block) -> 4 blocks/SM, occ ~50%.

#define TPB 256
#define PPB 128          // patches per block (2 threads per patch)
#define PAD 65           // floats per patch slot (conflict-free smem columns)

__device__ __forceinline__ float dct_c(int u, int i) {
    // fully-unrolled callers => compile-time constants => SASS immediates
    const float T[8][8] = {
        { 0.35355339f,  0.35355339f,  0.35355339f,  0.35355339f,  0.35355339f,  0.35355339f,  0.35355339f,  0.35355339f},
        { 0.49039264f,  0.41573481f,  0.27778512f,  0.09754516f, -0.09754516f, -0.27778512f, -0.41573481f, -0.49039264f},
        { 0.46193977f,  0.19134172f, -0.19134172f, -0.46193977f, -0.46193977f, -0.19134172f,  0.19134172f,  0.46193977f},
        { 0.41573481f, -0.09754516f, -0.49039264f, -0.27778512f,  0.27778512f,  0.49039264f,  0.09754516f, -0.41573481f},
        { 0.35355339f, -0.35355339f, -0.35355339f,  0.35355339f,  0.35355339f, -0.35355339f, -0.35355339f,  0.35355339f},
        { 0.27778512f, -0.49039264f,  0.09754516f,  0.41573481f, -0.41573481f, -0.09754516f,  0.49039264f, -0.27778512f},
        { 0.19134172f, -0.46193977f,  0.46193977f, -0.19134172f, -0.19134172f,  0.46193977f, -0.46193977f,  0.19134172f},
        { 0.09754516f, -0.27778512f,  0.41573481f, -0.49039264f,  0.49039264f, -0.41573481f,  0.27778512f, -0.09754516f},
    };
    return T[u][i];
}

__global__ void __launch_bounds__(TPB, 4)
dct_kernel(const float* __restrict__ in, float* __restrict__ out) {
    __shared__ float s[PPB * PAD];

    const size_t base = (size_t)blockIdx.x * (PPB * 64);
    const int t = threadIdx.x;

    // ---- Stage 1: coalesced global load -> padded smem (8 float4/thread) --
    const float4* __restrict__ in4 = (const float4*)(in + base);
#pragma unroll
    for (int n = 0; n < 8; ++n) {
        int idx4 = n * TPB + t;
        float4 v = in4[idx4];
        int e = idx4 * 4;          // float index within block's 8192 floats
        int p = e >> 6;            // patch
        int k = e & 63;            // element within patch
        float* dst = &s[p * PAD + k];
        dst[0] = v.x; dst[1] = v.y; dst[2] = v.z; dst[3] = v.w;
    }
    __syncthreads();

    // ---- Stage 2a: half-patch vertical transform --------------------------
    // patch = t>>1, half h = t&1. Thread computes tmp[ii][v] for output rows
    //   i = ii        (h=0)
    //   i = 7 - ii    (h=1)  via C[u][7-ii] = (-1)^u C[u][ii]
    const int p = t >> 1;
    const int h = t & 1;
    const float sgn = h ? -1.0f : 1.0f;   // branch-free sign for odd input rows
    float* X = &s[p * PAD];

    float tmp[4][8];
#pragma unroll
    for (int u = 0; u < 8; ++u) {
        float xr[8];
#pragma unroll
        for (int v = 0; v < 8; ++v) {
            float x = X[u * 8 + v];
            // fold (-1)^u into the h=1 half; (u&1) is compile-time here
            xr[v] = (u & 1) ? x * sgn : x;
        }
#pragma unroll
        for (int ii = 0; ii < 4; ++ii) {
            const float c = dct_c(u, ii);
#pragma unroll
            for (int v = 0; v < 8; ++v) {
                if (u == 0) tmp[ii][v] = c * xr[v];
                else        tmp[ii][v] = fmaf(c, xr[v], tmp[ii][v]);
            }
        }
    }

    // Partner thread (same warp) still reads rows this thread will overwrite.
    __syncwarp();

    // ---- Stage 2b: horizontal transform, write back in place --------------
#pragma unroll
    for (int ii = 0; ii < 4; ++ii) {
        const int i_t = h ? (7 - ii) : ii;
        float orow[8];
#pragma unroll
        for (int j = 0; j < 8; ++j) {
            float o = tmp[ii][0] * dct_c(0, j);
#pragma unroll
            for (int v = 1; v < 8; ++v)
                o = fmaf(tmp[ii][v], dct_c(v, j), o);
            orow[j] = o;
        }
        float* dst = &X[i_t * 8];
#pragma unroll
        for (int j = 0; j < 8; ++j) dst[j] = orow[j];
    }
    __syncthreads();

    // ---- Stage 3: padded smem -> coalesced global store -------------------
    float4* __restrict__ out4 = (float4*)(out + base);
#pragma unroll
    for (int n = 0; n < 8; ++n) {
        int idx4 = n * TPB + t;
        int e = idx4 * 4;
        int pp = e >> 6;
        int k = e & 63;
        const float* src = &s[pp * PAD + k];
        out4[idx4] = make_float4(src[0], src[1], src[2], src[3]);
    }
}

extern "C" void kernel_launch(void* const* d_in, const int* in_sizes, int n_in,
                              void* d_out, int out_size) {
    const float* in = (const float*)d_in[0];   // (8,3,1024,1024) fp32
    float* out = (float*)d_out;                // same shape fp32
    int total = in_sizes[0];                   // 25,165,824 floats
    int blocks = total / (PPB * 64);           // 3072 blocks
    dct_kernel<<<blocks, TPB>>>(in, out);
}

// round 4
// speedup vs baseline: 1.2217x; 1.1051x over previous
#include <cuda_runtime.h>
#include <cuda_bf16.h>

// 8x8 DCT on contiguous 64-float patches. out[f] = sum_u M[u][f] x[u] per dim,
// M[u][f] = s(u)*cos((2f+1)*u*pi/16) (this argument order is what the
// reference contracts with; verified rel_err 1.7e-7 in rounds 1/3).
//
// Round 4: issue-bound fix.
//  - PAD=68 -> all smem ops are LDS.128/STS.128 (quad bank = 17p+c, conflict-free)
//  - output-side butterfly via M[u][7-f] = (-1)^u M[u][f]: 40 ops / 8-pt DCT
//  - vertical stage split by v-columns (no duplicated patch reads, no divergence:
//    h = t>>7 is warp-uniform and only shifts addresses)

#define TPB 256
#define PPB 128          // patches per block
#define PAD 68           // floats per patch slot: 16B-aligned, 17p+c conflict-free

// M[u][f] = s(u) * cos((2f+1) u pi/16); same numeric table as before (dct_c(u,f)).
__device__ __forceinline__ float Mc(int u, int f) {
    const float T[8][8] = {
        { 0.35355339f,  0.35355339f,  0.35355339f,  0.35355339f,  0.35355339f,  0.35355339f,  0.35355339f,  0.35355339f},
        { 0.49039264f,  0.41573481f,  0.27778512f,  0.09754516f, -0.09754516f, -0.27778512f, -0.41573481f, -0.49039264f},
        { 0.46193977f,  0.19134172f, -0.19134172f, -0.46193977f, -0.46193977f, -0.19134172f,  0.19134172f,  0.46193977f},
        { 0.41573481f, -0.09754516f, -0.49039264f, -0.27778512f,  0.27778512f,  0.49039264f,  0.09754516f, -0.41573481f},
        { 0.35355339f, -0.35355339f, -0.35355339f,  0.35355339f,  0.35355339f, -0.35355339f, -0.35355339f,  0.35355339f},
        { 0.27778512f, -0.49039264f,  0.09754516f,  0.41573481f, -0.41573481f, -0.09754516f,  0.49039264f, -0.27778512f},
        { 0.19134172f, -0.46193977f,  0.46193977f, -0.19134172f, -0.19134172f,  0.46193977f, -0.46193977f,  0.19134172f},
        { 0.09754516f, -0.27778512f,  0.41573481f, -0.49039264f,  0.49039264f, -0.41573481f,  0.27778512f, -0.09754516f},
    };
    return T[u][f];
}

__device__ __forceinline__ float4 f4_add(float4 a, float4 b) {
    return make_float4(a.x+b.x, a.y+b.y, a.z+b.z, a.w+b.w);
}
__device__ __forceinline__ float4 f4_sub(float4 a, float4 b) {
    return make_float4(a.x-b.x, a.y-b.y, a.z-b.z, a.w-b.w);
}
__device__ __forceinline__ float4 f4_mul(float c, float4 a) {
    return make_float4(c*a.x, c*a.y, c*a.z, c*a.w);
}
__device__ __forceinline__ float4 f4_fma(float c, float4 a, float4 acc) {
    return make_float4(fmaf(c,a.x,acc.x), fmaf(c,a.y,acc.y),
                       fmaf(c,a.z,acc.z), fmaf(c,a.w,acc.w));
}

__global__ void __launch_bounds__(TPB, 4)
dct_kernel(const float* __restrict__ in, float* __restrict__ out) {
    __shared__ float s[PPB * PAD];

    const size_t base = (size_t)blockIdx.x * (PPB * 64);
    const int t = threadIdx.x;

    // ---- Stage 1: coalesced global load -> padded smem (STS.128) ----------
    const float4* __restrict__ in4 = (const float4*)(in + base);
#pragma unroll
    for (int n = 0; n < 8; ++n) {
        int idx4 = n * TPB + t;
        float4 v = in4[idx4];
        int e = idx4 * 4;
        int p = e >> 6;
        int k = e & 63;
        *(float4*)&s[p * PAD + k] = v;
    }
    __syncthreads();

    // Work split: patch p = t & 127, half h = t >> 7 (warp-uniform).
    const int p = t & 127;
    const int h = t >> 7;
    float* P = &s[p * PAD];

    // ---- Stage 2a: vertical 8-pt DCT on 4 columns (v = 4h..4h+3) ----------
    // y[f][v] = sum_u M[u][f] x[u][v]; butterfly: A=even-u part, B=odd-u part,
    // y[f]=A+B, y[7-f]=A-B. All 8 output rows computed; constants compile-time.
    {
        const int vo = 4 * h;
        float4 x[8];
#pragma unroll
        for (int u = 0; u < 8; ++u) x[u] = *(const float4*)&P[u * 8 + vo];

#pragma unroll
        for (int f = 0; f < 4; ++f) {
            float4 A = f4_mul(Mc(0, f), x[0]);
            A = f4_fma(Mc(2, f), x[2], A);
            A = f4_fma(Mc(4, f), x[4], A);
            A = f4_fma(Mc(6, f), x[6], A);
            float4 B = f4_mul(Mc(1, f), x[1]);
            B = f4_fma(Mc(3, f), x[3], B);
            B = f4_fma(Mc(5, f), x[5], B);
            B = f4_fma(Mc(7, f), x[7], B);
            *(float4*)&P[f * 8 + vo]       = f4_add(A, B);
            *(float4*)&P[(7 - f) * 8 + vo] = f4_sub(A, B);
        }
    }
    __syncthreads();

    // ---- Stage 2b: horizontal 8-pt DCT on 4 rows (r = 4h..4h+3) -----------
#pragma unroll
    for (int ii = 0; ii < 4; ++ii) {
        const int r = 4 * h + ii;          // warp-uniform address offset
        float4 lo = *(const float4*)&P[r * 8 + 0];
        float4 hi = *(const float4*)&P[r * 8 + 4];
        float tr[8] = {lo.x, lo.y, lo.z, lo.w, hi.x, hi.y, hi.z, hi.w};

        float o[8];
#pragma unroll
        for (int j = 0; j < 4; ++j) {
            float A = Mc(0, j) * tr[0];
            A = fmaf(Mc(2, j), tr[2], A);
            A = fmaf(Mc(4, j), tr[4], A);
            A = fmaf(Mc(6, j), tr[6], A);
            float B = Mc(1, j) * tr[1];
            B = fmaf(Mc(3, j), tr[3], B);
            B = fmaf(Mc(5, j), tr[5], B);
            B = fmaf(Mc(7, j), tr[7], B);
            o[j]     = A + B;
            o[7 - j] = A - B;
        }
        *(float4*)&P[r * 8 + 0] = make_float4(o[0], o[1], o[2], o[3]);
        *(float4*)&P[r * 8 + 4] = make_float4(o[4], o[5], o[6], o[7]);
    }
    __syncthreads();

    // ---- Stage 3: padded smem -> coalesced global store (LDS.128) ---------
    float4* __restrict__ out4 = (float4*)(out + base);
#pragma unroll
    for (int n = 0; n < 8; ++n) {
        int idx4 = n * TPB + t;
        int e = idx4 * 4;
        int pp = e >> 6;
        int k = e & 63;
        out4[idx4] = *(const float4*)&s[pp * PAD + k];
    }
}

extern "C" void kernel_launch(void* const* d_in, const int* in_sizes, int n_in,
                              void* d_out, int out_size) {
    const float* in = (const float*)d_in[0];   // (8,3,1024,1024) fp32
    float* out = (float*)d_out;                // same shape fp32
    int total = in_sizes[0];                   // 25,165,824 floats
    int blocks = total / (PPB * 64);           // 3072 blocks
    dct_kernel<<<blocks, TPB>>>(in, out);
}